// round 10
// baseline (speedup 1.0000x reference)
#include <cuda_runtime.h>
#include <cstdint>

// out[c,t,x,y] = mc ? k[t] : mp ? 0.5*k[t-1] : mn ? 0.25*k[t+1] : 0   (cases exclusive)
//
// Single launch, role-split CTAs:
//   CTAs 0..63 (the c=0 CTAs, wave-1 resident): compute the 2-bit selector
//   pair table g_sel2 (1 MB, L2-resident) for their 256 g-columns, then
//   release a device counter (threadfence + atomicAdd = release).
//   All other CTAs: load first k element, gate on the counter
//   (ld.acquire.gpu spin in tid0 + __syncthreads), then run the pure
//   1-load/1-store rolling stream (identical mapping to the best 2-kernel
//   variant: 1 channel x 256 consecutive float4-groups per CTA).
// Per-launch counters are reset by the last CTA to finish -> every launch
// sees identical initial state (graph-replay safe, deterministic).

#define ALPHA 0.5f
#define BETA  0.25f

constexpr int NC  = 32;
constexpr int NT  = 64;
constexpr int PLANE4 = 256 * 256 / 4;   // 16384 float4 groups per t-slice
constexpr int COLS   = NC * PLANE4;     // 524288 threads
constexpr int NPAIR  = NT / 8;          // 8 uint2 selector pairs per g
constexpr int NCTA   = COLS / 256;      // 2048
constexpr int PRE_CTAS = PLANE4 / 256;  // 64 (== the c=0 CTAs)

__device__ uint2 g_sel2[NPAIR * PLANE4];   // [pair h][g], 1 MB
__device__ int   g_done   = 0;             // pre-CTAs finished
__device__ int   g_passed = 0;             // CTAs fully finished (for reset)

__device__ __forceinline__ uint32_t code1(int mc, int mp, int mn) {
    return mc ? 1u : (mp ? 2u : (mn ? 3u : 0u));
}

__device__ __forceinline__ float pick(uint32_t c, float kc, float kp, float kn) {
    return (c == 1u) ? kc
         : (c == 2u) ? ALPHA * kp
         : (c == 3u) ? BETA * kn
         : 0.0f;
}

__global__ void __launch_bounds__(256, 8)
dsb_one(const float4* __restrict__ k,
        const int4*   __restrict__ mask,
        float4*       __restrict__ out)
{
    const int tid = threadIdx.x;
    const int bx  = blockIdx.x;
    const int gid = bx * 256 + tid;
    const int g   = gid & (PLANE4 - 1);
    const int c   = gid >> 14;

    // ---- selector producer role: CTAs 0..63 (c == 0) ----
    if (bx < PRE_CTAS) {
        // rolling walk over t for column g; 64 coalesced int4 loads
        int4 mp = make_int4(0, 0, 0, 0);
        int4 mc = __ldg(&mask[g]);
        #pragma unroll 1
        for (int h = 0; h < NPAIR; h++) {
            uint32_t wa = 0u, wb = 0u;
            #pragma unroll
            for (int i = 0; i < 8; i++) {
                const int t = h * 8 + i;
                int4 mn = (t < NT - 1) ? __ldg(&mask[(t + 1) * PLANE4 + g])
                                       : make_int4(0, 0, 0, 0);
                uint32_t byte =  code1(mc.x, mp.x, mn.x)
                              | (code1(mc.y, mp.y, mn.y) << 2)
                              | (code1(mc.z, mp.z, mn.z) << 4)
                              | (code1(mc.w, mp.w, mn.w) << 6);
                if (i < 4) wa |= byte << (i * 8);
                else       wb |= byte << ((i - 4) * 8);
                mp = mc; mc = mn;
            }
            g_sel2[h * PLANE4 + g] = make_uint2(wa, wb);   // coalesced 8B store
        }
        __threadfence();                  // release: sel writes before counter
        __syncthreads();                  // whole CTA's stores fenced
        if (tid == 0) atomicAdd(&g_done, 1);
    }

    // ---- stream setup (before gate: overlaps producer phase) ----
    const float4* kk = k   + (size_t)c * NT * PLANE4 + g;
    float4*       oo = out + (size_t)c * NT * PLANE4 + g;

    float4 kp = make_float4(0.f, 0.f, 0.f, 0.f);
    float4 kc = __ldcs(kk);

    // ---- gate: consumers wait until all 64 producer CTAs released ----
    if (bx >= PRE_CTAS) {
        if (tid == 0) {
            int v;
            do {
                asm volatile("ld.global.acquire.gpu.s32 %0, [%1];"
                             : "=r"(v) : "l"(&g_done));
            } while (v < PRE_CTAS);
        }
        __syncthreads();
    }

    // ---- main stream: rolling registers over t ----
    int t = 0;
    #pragma unroll 1
    for (int h = 0; h < NPAIR; h++) {
        const uint2 s = __ldg(&g_sel2[h * PLANE4 + g]);   // L2-resident
        uint32_t words[2] = { s.x, s.y };
        #pragma unroll
        for (int j = 0; j < 2; j++) {
            const uint32_t wrd = words[j];
            #pragma unroll
            for (int tt = 0; tt < 4; tt++) {
                float4 kn = (t < NT - 1) ? __ldcs(kk + (t + 1) * PLANE4)
                                         : make_float4(0.f, 0.f, 0.f, 0.f);

                const uint32_t byte = (wrd >> (tt * 8)) & 0xFFu;
                float4 o;
                o.x = pick( byte       & 3u, kc.x, kp.x, kn.x);
                o.y = pick((byte >> 2) & 3u, kc.y, kp.y, kn.y);
                o.z = pick((byte >> 4) & 3u, kc.z, kp.z, kn.z);
                o.w = pick((byte >> 6) & 3u, kc.w, kp.w, kn.w);

                __stcs(oo + t * PLANE4, o);

                kp = kc; kc = kn;
                t++;
            }
        }
    }

    // ---- per-launch state reset: last CTA to finish clears the counters ----
    __syncthreads();
    if (tid == 0) {
        const int p = atomicAdd(&g_passed, 1);
        if (p == NCTA - 1) {
            g_done   = 0;
            g_passed = 0;
            __threadfence();
        }
    }
}

extern "C" void kernel_launch(void* const* d_in, const int* in_sizes, int n_in,
                              void* d_out, int out_size)
{
    const float4* k    = (const float4*)d_in[0];
    const int4*   mask = (const int4*)d_in[1];
    float4*       out  = (float4*)d_out;

    dsb_one<<<NCTA, 256>>>(k, mask, out);
}

// round 11
// speedup vs baseline: 1.0948x; 1.0948x over previous
#include <cuda_runtime.h>
#include <cstdint>

// out[c,t,x,y] = mc ? k[t] : mp ? 0.5*k[t-1] : mn ? 0.25*k[t+1] : 0   (cases exclusive)
// Mask is channel-invariant -> precompute 2-bit selector per (t, xy) into a
// 1 MB L2-resident pair-major table sel2[h][g] (uint2, h = t/8).
// Main kernel: pure 1-load/1-store rolling stream; 512-thread CTAs spanning
// 512 consecutive float4-groups (8 KB contiguous per t-access) for DRAM row
// locality. PDL with sync at kernel top hides the launch gap.

#define ALPHA 0.5f
#define BETA  0.25f

constexpr int NC  = 32;
constexpr int NT  = 64;
constexpr int PLANE4 = 256 * 256 / 4;   // 16384 float4 groups per t-slice
constexpr int COLS   = NC * PLANE4;     // 524288 stream threads
constexpr int NPAIR  = NT / 8;          // 8 uint2 selector pairs per g
constexpr int TPB    = 512;             // stream CTA size
constexpr int NCTA   = COLS / TPB;      // 1024

__device__ uint2 g_sel2[NPAIR * PLANE4];  // [pair h][g], 1 MB

__device__ __forceinline__ uint32_t code1(int mc, int mp, int mn) {
    return mc ? 1u : (mp ? 2u : (mn ? 3u : 0u));
}

// One thread per (pair h, g): computes 8 t-steps (t = 8h..8h+7).
__global__ void __launch_bounds__(256)
pre_kernel(const int4* __restrict__ mask)
{
    const int tidg = blockIdx.x * blockDim.x + threadIdx.x;  // 0 .. 8*PLANE4-1
    const int g = tidg & (PLANE4 - 1);
    const int h = tidg >> 14;            // 0..7
    const int t0 = h * 8;

    int4 mbuf[10];
    #pragma unroll
    for (int i = 0; i < 10; i++) {
        const int t = t0 - 1 + i;
        mbuf[i] = (t >= 0 && t < NT) ? __ldg(&mask[t * PLANE4 + g])
                                     : make_int4(0, 0, 0, 0);
    }

    uint32_t w[2] = {0u, 0u};
    #pragma unroll
    for (int i = 0; i < 8; i++) {
        const int4 mp = mbuf[i];
        const int4 mc = mbuf[i + 1];
        const int4 mn = mbuf[i + 2];
        uint32_t byte =  code1(mc.x, mp.x, mn.x)
                      | (code1(mc.y, mp.y, mn.y) << 2)
                      | (code1(mc.z, mp.z, mn.z) << 4)
                      | (code1(mc.w, mp.w, mn.w) << 6);
        w[i >> 2] |= byte << ((i & 3) * 8);
    }

    g_sel2[h * PLANE4 + g] = make_uint2(w[0], w[1]);   // coalesced 8B store

#if __CUDA_ARCH__ >= 900
    cudaTriggerProgrammaticLaunchCompletion();
#endif
}

__device__ __forceinline__ float pick(uint32_t c, float kc, float kp, float kn) {
    return (c == 1u) ? kc
         : (c == 2u) ? ALPHA * kp
         : (c == 3u) ? BETA * kn
         : 0.0f;
}

__global__ void __launch_bounds__(TPB, 4)
dsb_kernel(const float4* __restrict__ k, float4* __restrict__ out)
{
#if __CUDA_ARCH__ >= 900
    cudaGridDependencySynchronize();     // before any memory traffic
#endif

    const int gid = blockIdx.x * TPB + threadIdx.x;
    const int g = gid & (PLANE4 - 1);
    const int c = gid >> 14;

    const float4* kk = k   + (size_t)c * NT * PLANE4 + g;
    float4*       oo = out + (size_t)c * NT * PLANE4 + g;

    float4 kp = make_float4(0.f, 0.f, 0.f, 0.f);
    float4 kc = __ldcs(kk);

    int t = 0;
    #pragma unroll 1
    for (int h = 0; h < NPAIR; h++) {
        const uint2 s = __ldg(&g_sel2[h * PLANE4 + g]);   // L2-resident
        uint32_t words[2] = { s.x, s.y };
        #pragma unroll
        for (int j = 0; j < 2; j++) {
            const uint32_t wrd = words[j];
            #pragma unroll
            for (int tt = 0; tt < 4; tt++) {
                float4 kn = (t < NT - 1) ? __ldcs(kk + (t + 1) * PLANE4)
                                         : make_float4(0.f, 0.f, 0.f, 0.f);

                const uint32_t byte = (wrd >> (tt * 8)) & 0xFFu;
                float4 o;
                o.x = pick( byte       & 3u, kc.x, kp.x, kn.x);
                o.y = pick((byte >> 2) & 3u, kc.y, kp.y, kn.y);
                o.z = pick((byte >> 4) & 3u, kc.z, kp.z, kn.z);
                o.w = pick((byte >> 6) & 3u, kc.w, kp.w, kn.w);

                __stcs(oo + t * PLANE4, o);

                kp = kc; kc = kn;
                t++;
            }
        }
    }
}

extern "C" void kernel_launch(void* const* d_in, const int* in_sizes, int n_in,
                              void* d_out, int out_size)
{
    const float4* k    = (const float4*)d_in[0];
    const int4*   mask = (const int4*)d_in[1];
    float4*       out  = (float4*)d_out;

    pre_kernel<<<(8 * PLANE4) / 256, 256>>>(mask);

    cudaLaunchConfig_t cfg = {};
    cfg.gridDim  = dim3(NCTA);
    cfg.blockDim = dim3(TPB);
    cfg.dynamicSmemBytes = 0;
    cfg.stream = 0;
    cudaLaunchAttribute attr[1];
    attr[0].id = cudaLaunchAttributeProgrammaticStreamSerialization;
    attr[0].val.programmaticStreamSerializationAllowed = 1;
    cfg.attrs = attr;
    cfg.numAttrs = 1;
    cudaError_t err = cudaLaunchKernelEx(&cfg, dsb_kernel, k, out);
    if (err != cudaSuccess) {
        dsb_kernel<<<NCTA, TPB>>>(k, out);
    }
}